// round 4
// baseline (speedup 1.0000x reference)
#include <cuda_runtime.h>
#include <math.h>

#define S 2048
#define E 4096
#define H 32
#define D 128
#define NKEEP 205      // S - int(S*0.9)
#define CAP 256        // max kept kv per row (>= NKEEP + tie slack)

// ---------------- device scratch (no allocations allowed) ----------------
__device__ float g_Q[(size_t)S * E];
__device__ float g_K[(size_t)S * E];
__device__ float g_V[(size_t)S * E];
__device__ float g_Qr[(size_t)S * E];
__device__ float g_Kr[(size_t)S * E];
__device__ float g_attn[(size_t)S * E];
__device__ float g_draft[(size_t)H * S * S];          // 512 MB scratch
__device__ unsigned short g_idx[(size_t)H * S * CAP]; // selected kv indices
__device__ int g_cnt[H * S];
__device__ float g_cos[S * D];
__device__ float g_sin[S * D];

// ---------------- RoPE cache ----------------
__global__ void rope_cache_kernel()
{
    int s = blockIdx.x, d = threadIdx.x;      // d in [0,64)
    float invf = (float)(1.0 / pow(10000.0, (double)(2 * d) / 128.0));
    float ang = (float)s * invf;              // fp32 angle, matching jnp outer()
    double a = (double)ang;
    float c = (float)cos(a), sn = (float)sin(a);
    g_cos[s * D + d] = c;  g_cos[s * D + d + 64] = c;
    g_sin[s * D + d] = sn; g_sin[s * D + d + 64] = sn;
}

// ---------------- dense SGEMM (NN, row-major): C[M,N] = A[M,K] @ B[K,N] ----------------
// 128x128 tile, 8x8 microtile, K-step 8, register-prefetch software pipeline.
__global__ __launch_bounds__(256) void sgemm_nn(const float* __restrict__ A,
                                                const float* __restrict__ B,
                                                float* __restrict__ C,
                                                int M, int N, int K)
{
    __shared__ __align__(16) float As[8][128];   // transposed A tile
    __shared__ __align__(16) float Bs[8][128];
    const int tid = threadIdx.x;
    const int brow = blockIdx.y * 128;
    const int bcol = blockIdx.x * 128;
    const int tr = (tid >> 4) * 8;
    const int tc = (tid & 15) * 8;
    const int arow = tid >> 1;            // 0..127
    const int acol = (tid & 1) * 4;       // 0 or 4
    const int brw  = tid >> 5;            // 0..7
    const int bcl  = (tid & 31) * 4;      // 0..124
    const float* Ag = A + (size_t)(brow + arow) * K + acol;
    const float* Bg = B + (size_t)brw * N + bcol + bcl;
    float acc[8][8];
#pragma unroll
    for (int i = 0; i < 8; ++i)
#pragma unroll
        for (int j = 0; j < 8; ++j) acc[i][j] = 0.f;

    float4 av = *(const float4*)(Ag);
    float4 bv = *(const float4*)(Bg);
    for (int k0 = 0; k0 < K; k0 += 8) {
        As[acol + 0][arow] = av.x; As[acol + 1][arow] = av.y;
        As[acol + 2][arow] = av.z; As[acol + 3][arow] = av.w;
        *(float4*)&Bs[brw][bcl] = bv;
        __syncthreads();
        if (k0 + 8 < K) {                              // prefetch next tile
            av = *(const float4*)(Ag + k0 + 8);
            bv = *(const float4*)(Bg + (size_t)(k0 + 8) * N);
        }
#pragma unroll
        for (int k = 0; k < 8; ++k) {
            float ra[8], rb[8];
            *(float4*)&ra[0] = *(const float4*)&As[k][tr];
            *(float4*)&ra[4] = *(const float4*)&As[k][tr + 4];
            *(float4*)&rb[0] = *(const float4*)&Bs[k][tc];
            *(float4*)&rb[4] = *(const float4*)&Bs[k][tc + 4];
#pragma unroll
            for (int i = 0; i < 8; ++i)
#pragma unroll
                for (int j = 0; j < 8; ++j)
                    acc[i][j] = fmaf(ra[i], rb[j], acc[i][j]);
        }
        __syncthreads();
    }
#pragma unroll
    for (int i = 0; i < 8; ++i) {
        float* Cp = C + (size_t)(brow + tr + i) * N + bcol + tc;
        *(float4*)Cp       = make_float4(acc[i][0], acc[i][1], acc[i][2], acc[i][3]);
        *(float4*)(Cp + 4) = make_float4(acc[i][4], acc[i][5], acc[i][6], acc[i][7]);
    }
}

// ---------------- RoPE apply: Qr/Kr from Q/K ----------------
__global__ void rope_apply_kernel()
{
    int s = blockIdx.x;
    for (int e = threadIdx.x; e < E; e += blockDim.x) {
        int d = e & (D - 1);
        float c = g_cos[s * D + d], sn = g_sin[s * D + d];
        size_t o = (size_t)s * E + e;
        int ep = (d < 64) ? e + 64 : e - 64;
        size_t op = (size_t)s * E + ep;
        float sgn = (d < 64) ? -1.f : 1.f;
        g_Qr[o] = g_Q[o] * c + sgn * g_Q[op] * sn;
        g_Kr[o] = g_K[o] * c + sgn * g_K[op] * sn;
    }
}

// ---------------- draft = Q_h @ K_h^T (pre-RoPE), causal tiles only ----------------
__global__ __launch_bounds__(256) void draft_gemm_kernel()
{
    int jt = blockIdx.x, it = blockIdx.y, h = blockIdx.z;
    if (jt > it) return;  // strictly above diagonal: never read by top-k
    __shared__ __align__(16) float Qs[32][128];
    __shared__ __align__(16) float Ks[32][128];
    const int tid = threadIdx.x;
    const float* Aq = g_Q + (size_t)(it * 128) * E + h * D;
    const float* Ak = g_K + (size_t)(jt * 128) * E + h * D;
    const int tr = (tid >> 4) * 8, tc = (tid & 15) * 8;
    float acc[8][8];
#pragma unroll
    for (int i = 0; i < 8; ++i)
#pragma unroll
        for (int j = 0; j < 8; ++j) acc[i][j] = 0.f;

    for (int k0 = 0; k0 < D; k0 += 32) {
#pragma unroll
        for (int p = 0; p < 4; ++p) {
            int lin = p * 256 + tid;
            int r = lin >> 3;
            int c4 = (lin & 7) * 4;
            float4 qa = *(const float4*)(Aq + (size_t)r * E + k0 + c4);
            Qs[c4 + 0][r] = qa.x; Qs[c4 + 1][r] = qa.y;
            Qs[c4 + 2][r] = qa.z; Qs[c4 + 3][r] = qa.w;
            float4 ka = *(const float4*)(Ak + (size_t)r * E + k0 + c4);
            Ks[c4 + 0][r] = ka.x; Ks[c4 + 1][r] = ka.y;
            Ks[c4 + 2][r] = ka.z; Ks[c4 + 3][r] = ka.w;
        }
        __syncthreads();
#pragma unroll
        for (int k = 0; k < 32; ++k) {
            float ra[8], rb[8];
            *(float4*)&ra[0] = *(const float4*)&Qs[k][tr];
            *(float4*)&ra[4] = *(const float4*)&Qs[k][tr + 4];
            *(float4*)&rb[0] = *(const float4*)&Ks[k][tc];
            *(float4*)&rb[4] = *(const float4*)&Ks[k][tc + 4];
#pragma unroll
            for (int i = 0; i < 8; ++i)
#pragma unroll
                for (int j = 0; j < 8; ++j)
                    acc[i][j] = fmaf(ra[i], rb[j], acc[i][j]);
        }
        __syncthreads();
    }
    float* Cb = g_draft + ((size_t)h * S + it * 128 + tr) * S + jt * 128 + tc;
#pragma unroll
    for (int i = 0; i < 8; ++i) {
        *(float4*)(Cb + (size_t)i * S)     = make_float4(acc[i][0], acc[i][1], acc[i][2], acc[i][3]);
        *(float4*)(Cb + (size_t)i * S + 4) = make_float4(acc[i][4], acc[i][5], acc[i][6], acc[i][7]);
    }
}

// ---------------- per-row top-NKEEP selection (exact radix-select on ordered uints) ----------------
__global__ __launch_bounds__(256) void topk_kernel()
{
    int q = blockIdx.x, h = blockIdx.y, tid = threadIdx.x;
    __shared__ unsigned keys[2048];
    __shared__ int aux[257];
    __shared__ unsigned sh_prefix;
    __shared__ int sh_k, sh_total;
    size_t base = ((size_t)h * S + q) * CAP;
    int n = q + 1;                     // causal-valid count
    if (n <= NKEEP) {                  // all valid positions kept
        for (int j = tid; j < n; j += 256) g_idx[base + j] = (unsigned short)j;
        if (tid == 0) g_cnt[h * S + q] = n;
        return;
    }
    const float* row = g_draft + ((size_t)h * S + q) * S;
    for (int j = tid; j < n; j += 256) {
        unsigned u = __float_as_uint(row[j]);
        keys[j] = (u & 0x80000000u) ? ~u : (u | 0x80000000u);  // order-preserving map
    }
    __syncthreads();
    unsigned prefix = 0, himask = 0;
    int kk = NKEEP;
    for (int byte = 3; byte >= 0; --byte) {
        if (tid < 256) aux[tid] = 0;
        __syncthreads();
        for (int j = tid; j < n; j += 256) {
            unsigned u = keys[j];
            if ((u & himask) == prefix)
                atomicAdd(&aux[(u >> (byte * 8)) & 255], 1);
        }
        __syncthreads();
        if (tid == 0) {
            int cum = 0, b = 255;
            for (; b > 0; --b) {
                int c = aux[b];
                if (cum + c >= kk) break;
                cum += c;
            }
            sh_prefix = prefix | ((unsigned)b << (byte * 8));
            sh_k = kk - cum;
        }
        __syncthreads();
        prefix = sh_prefix;
        kk = sh_k;
        himask |= 0xFFu << (byte * 8);
        __syncthreads();
    }
    // prefix == ordered key of the NKEEP-th largest. Ordered deterministic compaction.
    int seg = (n + 255) >> 8;
    int j0 = tid * seg;
    int j1 = min(j0 + seg, n);
    int cnt = 0;
    for (int j = j0; j < j1; ++j) if (keys[j] >= prefix) cnt++;
    aux[tid] = cnt;
    __syncthreads();
    if (tid == 0) {
        int run = 0;
        for (int i = 0; i < 256; ++i) { int c = aux[i]; aux[i] = run; run += c; }
        sh_total = run;
    }
    __syncthreads();
    int p = aux[tid];
    for (int j = j0; j < j1; ++j)
        if (keys[j] >= prefix) { if (p < CAP) g_idx[base + p] = (unsigned short)j; ++p; }
    if (tid == 0) g_cnt[h * S + q] = min(sh_total, CAP);
}

// ---------------- sparse attention: gather selected kv, softmax, PV ----------------
__global__ __launch_bounds__(128) void attn_kernel()
{
    int q = blockIdx.x, h = blockIdx.y, tid = threadIdx.x;
    __shared__ __align__(16) float qv[D];
    __shared__ float sc[CAP];
    __shared__ unsigned short lj[CAP];
    __shared__ float red[4];
    int n = g_cnt[h * S + q];
    qv[tid] = g_Qr[(size_t)q * E + h * D + tid];
    for (int i = tid; i < n; i += 128) lj[i] = g_idx[((size_t)h * S + q) * CAP + i];
    __syncthreads();
    int lane = tid & 31, w = tid >> 5;
    float4 qf = *(const float4*)&qv[lane * 4];
    for (int i = w; i < n; i += 4) {     // one warp per selected key
        const float* kr = g_Kr + (size_t)lj[i] * E + h * D + lane * 4;
        float4 kf = *(const float4*)kr;
        float s = qf.x * kf.x + qf.y * kf.y + qf.z * kf.z + qf.w * kf.w;
#pragma unroll
        for (int o = 16; o; o >>= 1) s += __shfl_xor_sync(0xffffffffu, s, o);
        if (lane == 0) sc[i] = s * 0.08838834764831845f;  // 1/sqrt(128)
    }
    __syncthreads();
    float mx = -INFINITY;
    for (int i = tid; i < n; i += 128) mx = fmaxf(mx, sc[i]);
#pragma unroll
    for (int o = 16; o; o >>= 1) mx = fmaxf(mx, __shfl_xor_sync(0xffffffffu, mx, o));
    if (lane == 0) red[w] = mx;
    __syncthreads();
    mx = fmaxf(fmaxf(red[0], red[1]), fmaxf(red[2], red[3]));
    __syncthreads();
    float sum = 0.f;
    for (int i = tid; i < n; i += 128) { float e = expf(sc[i] - mx); sc[i] = e; sum += e; }
#pragma unroll
    for (int o = 16; o; o >>= 1) sum += __shfl_xor_sync(0xffffffffu, sum, o);
    if (lane == 0) red[w] = sum;
    __syncthreads();
    sum = red[0] + red[1] + red[2] + red[3];
    float inv = 1.f / sum;
    // PV: thread tid == head-dim d; coalesced V row gathers
    float acc = 0.f;
    const float* Vb = g_V + h * D + tid;
    for (int i = 0; i < n; ++i)
        acc = fmaf(sc[i], Vb[(size_t)lj[i] * E], acc);
    g_attn[(size_t)q * E + h * D + tid] = acc * inv;
}

// ---------------- host ----------------
extern "C" void kernel_launch(void* const* d_in, const int* in_sizes, int n_in,
                              void* d_out, int out_size)
{
    const float* X  = (const float*)d_in[0];
    const float* Wq = (const float*)d_in[1];
    const float* Wk = (const float*)d_in[2];
    const float* Wv = (const float*)d_in[3];
    const float* Wo = (const float*)d_in[4];
    float* out = (float*)d_out;

    float *pQ, *pK, *pV, *pAt;
    cudaGetSymbolAddress((void**)&pQ, g_Q);
    cudaGetSymbolAddress((void**)&pK, g_K);
    cudaGetSymbolAddress((void**)&pV, g_V);
    cudaGetSymbolAddress((void**)&pAt, g_attn);

    dim3 gg(E / 128, S / 128);
    rope_cache_kernel<<<S, 64>>>();
    sgemm_nn<<<gg, 256>>>(X, Wq, pQ, S, E, E);
    sgemm_nn<<<gg, 256>>>(X, Wk, pK, S, E, E);
    sgemm_nn<<<gg, 256>>>(X, Wv, pV, S, E, E);
    rope_apply_kernel<<<S, 256>>>();
    draft_gemm_kernel<<<dim3(16, 16, 32), 256>>>();
    topk_kernel<<<dim3(S, H), 256>>>();
    attn_kernel<<<dim3(S, H), 128>>>();
    sgemm_nn<<<gg, 256>>>(pAt, Wo, out, S, E, E);
}

// round 12
// speedup vs baseline: 1.3577x; 1.3577x over previous
#include <cuda_runtime.h>
#include <cuda_bf16.h>
#include <math.h>
#include <stdint.h>

#define S 2048
#define E 4096
#define H 32
#define D 128
#define NKEEP 205      // S - int(S*0.9)
#define CAP 256        // max kept kv per row

// ---------------- device scratch (no allocations allowed) ----------------
__device__ float g_Q[(size_t)S * E];
__device__ float g_K[(size_t)S * E];
__device__ float g_V[(size_t)S * E];
__device__ float g_Qr[(size_t)S * E];
__device__ float g_Kr[(size_t)S * E];
__device__ float g_attn[(size_t)S * E];
__device__ float g_draft[(size_t)H * S * S];          // 512 MB scratch
__device__ unsigned short g_idx[(size_t)H * S * CAP];
__device__ int g_cnt[H * S];
__device__ float g_cos[S * D];
__device__ float g_sin[S * D];

// bf16 hi/lo splits (V projection + output projection only — non-selection-critical)
__device__ __nv_bfloat16 g_Xhi[(size_t)S * E], g_Xlo[(size_t)S * E];
__device__ __nv_bfloat16 g_Ahi[(size_t)S * E], g_Alo[(size_t)S * E];
__device__ __nv_bfloat16 g_Wvhi[(size_t)E * E], g_Wvlo[(size_t)E * E];
__device__ __nv_bfloat16 g_Wohi[(size_t)E * E], g_Wolo[(size_t)E * E];

// ---------------- PTX helpers (compute_103-safe) ----------------
__device__ __forceinline__ uint32_t smem_u32(const void* p) {
    uint32_t a;
    asm("{ .reg .u64 t; cvta.to.shared.u64 t, %1; cvt.u32.u64 %0, t; }" : "=r"(a) : "l"(p));
    return a;
}
__device__ __forceinline__ void cp16(uint32_t dst, const void* src) {
    asm volatile("cp.async.cg.shared.global [%0], [%1], 16;" :: "r"(dst), "l"(src) : "memory");
}
#define CP_COMMIT() asm volatile("cp.async.commit_group;" ::: "memory")
#define CP_WAIT1()  asm volatile("cp.async.wait_group 1;" ::: "memory")

__device__ __forceinline__ void ldm_x4(uint32_t* r, uint32_t addr) {
    asm volatile("ldmatrix.sync.aligned.m8n8.x4.shared.b16 {%0,%1,%2,%3}, [%4];"
        : "=r"(r[0]), "=r"(r[1]), "=r"(r[2]), "=r"(r[3]) : "r"(addr));
}
__device__ __forceinline__ void ldm_x4_t(uint32_t* r, uint32_t addr) {
    asm volatile("ldmatrix.sync.aligned.m8n8.x4.trans.shared.b16 {%0,%1,%2,%3}, [%4];"
        : "=r"(r[0]), "=r"(r[1]), "=r"(r[2]), "=r"(r[3]) : "r"(addr));
}
__device__ __forceinline__ void mma16816(float* d, const uint32_t* a, const uint32_t* b) {
    asm volatile("mma.sync.aligned.m16n8k16.row.col.f32.bf16.bf16.f32 "
        "{%0,%1,%2,%3}, {%4,%5,%6,%7}, {%8,%9}, {%0,%1,%2,%3};"
        : "+f"(d[0]), "+f"(d[1]), "+f"(d[2]), "+f"(d[3])
        : "r"(a[0]), "r"(a[1]), "r"(a[2]), "r"(a[3]), "r"(b[0]), "r"(b[1]));
}

// ---------------- RoPE cache ----------------
__global__ void rope_cache_kernel()
{
    int s = blockIdx.x, d = threadIdx.x;      // d in [0,64)
    float invf = (float)(1.0 / pow(10000.0, (double)(2 * d) / 128.0));
    float ang = (float)s * invf;
    double a = (double)ang;
    float c = (float)cos(a), sn = (float)sin(a);
    g_cos[s * D + d] = c;  g_cos[s * D + d + 64] = c;
    g_sin[s * D + d] = sn; g_sin[s * D + d + 64] = sn;
}

// ---------------- fp32 -> bf16 hi/lo split ----------------
__global__ __launch_bounds__(256) void cvt_kernel(const float* __restrict__ x,
                                                  __nv_bfloat16* __restrict__ hi,
                                                  __nv_bfloat16* __restrict__ lo, int n4)
{
    int i = blockIdx.x * blockDim.x + threadIdx.x;
    if (i >= n4) return;
    float4 v = ((const float4*)x)[i];
    __nv_bfloat16 h0 = __float2bfloat16(v.x), h1 = __float2bfloat16(v.y);
    __nv_bfloat16 h2 = __float2bfloat16(v.z), h3 = __float2bfloat16(v.w);
    __nv_bfloat16 l0 = __float2bfloat16(v.x - __bfloat162float(h0));
    __nv_bfloat16 l1 = __float2bfloat16(v.y - __bfloat162float(h1));
    __nv_bfloat16 l2 = __float2bfloat16(v.z - __bfloat162float(h2));
    __nv_bfloat16 l3 = __float2bfloat16(v.w - __bfloat162float(h3));
    ((__nv_bfloat162*)hi)[2 * i]     = __halves2bfloat162(h0, h1);
    ((__nv_bfloat162*)hi)[2 * i + 1] = __halves2bfloat162(h2, h3);
    ((__nv_bfloat162*)lo)[2 * i]     = __halves2bfloat162(l0, l1);
    ((__nv_bfloat162*)lo)[2 * i + 1] = __halves2bfloat162(l2, l3);
}

// ---------------- fp32 SIMT SGEMM (Q/K projections — selection-critical) ----------------
// 128x128 tile, 8x8 microtile, K-step 8, register-prefetch software pipeline.  (R4-proven)
__global__ __launch_bounds__(256) void sgemm_nn(const float* __restrict__ A,
                                                const float* __restrict__ B,
                                                float* __restrict__ C,
                                                int M, int N, int K)
{
    __shared__ __align__(16) float As[8][128];   // transposed A tile
    __shared__ __align__(16) float Bs[8][128];
    const int tid = threadIdx.x;
    const int brow = blockIdx.y * 128;
    const int bcol = blockIdx.x * 128;
    const int tr = (tid >> 4) * 8;
    const int tc = (tid & 15) * 8;
    const int arow = tid >> 1;
    const int acol = (tid & 1) * 4;
    const int brw  = tid >> 5;
    const int bcl  = (tid & 31) * 4;
    const float* Ag = A + (size_t)(brow + arow) * K + acol;
    const float* Bg = B + (size_t)brw * N + bcol + bcl;
    float acc[8][8];
#pragma unroll
    for (int i = 0; i < 8; ++i)
#pragma unroll
        for (int j = 0; j < 8; ++j) acc[i][j] = 0.f;

    float4 av = *(const float4*)(Ag);
    float4 bv = *(const float4*)(Bg);
    for (int k0 = 0; k0 < K; k0 += 8) {
        As[acol + 0][arow] = av.x; As[acol + 1][arow] = av.y;
        As[acol + 2][arow] = av.z; As[acol + 3][arow] = av.w;
        *(float4*)&Bs[brw][bcl] = bv;
        __syncthreads();
        if (k0 + 8 < K) {
            av = *(const float4*)(Ag + k0 + 8);
            bv = *(const float4*)(Bg + (size_t)(k0 + 8) * N);
        }
#pragma unroll
        for (int k = 0; k < 8; ++k) {
            float ra[8], rb[8];
            *(float4*)&ra[0] = *(const float4*)&As[k][tr];
            *(float4*)&ra[4] = *(const float4*)&As[k][tr + 4];
            *(float4*)&rb[0] = *(const float4*)&Bs[k][tc];
            *(float4*)&rb[4] = *(const float4*)&Bs[k][tc + 4];
#pragma unroll
            for (int i = 0; i < 8; ++i)
#pragma unroll
                for (int j = 0; j < 8; ++j)
                    acc[i][j] = fmaf(ra[i], rb[j], acc[i][j]);
        }
        __syncthreads();
    }
#pragma unroll
    for (int i = 0; i < 8; ++i) {
        float* Cp = C + (size_t)(brow + tr + i) * N + bcol + tc;
        *(float4*)Cp       = make_float4(acc[i][0], acc[i][1], acc[i][2], acc[i][3]);
        *(float4*)(Cp + 4) = make_float4(acc[i][4], acc[i][5], acc[i][6], acc[i][7]);
    }
}

// ---------------- fp32 draft = Q_h @ K_h^T (pre-RoPE), causal tiles only (R4-proven) ----------------
__global__ __launch_bounds__(256) void draft_gemm_kernel()
{
    int jt = blockIdx.x, it = blockIdx.y, h = blockIdx.z;
    if (jt > it) return;
    __shared__ __align__(16) float Qs[32][128];
    __shared__ __align__(16) float Ks[32][128];
    const int tid = threadIdx.x;
    const float* Aq = g_Q + (size_t)(it * 128) * E + h * D;
    const float* Ak = g_K + (size_t)(jt * 128) * E + h * D;
    const int tr = (tid >> 4) * 8, tc = (tid & 15) * 8;
    float acc[8][8];
#pragma unroll
    for (int i = 0; i < 8; ++i)
#pragma unroll
        for (int j = 0; j < 8; ++j) acc[i][j] = 0.f;

    for (int k0 = 0; k0 < D; k0 += 32) {
#pragma unroll
        for (int p = 0; p < 4; ++p) {
            int lin = p * 256 + tid;
            int r = lin >> 3;
            int c4 = (lin & 7) * 4;
            float4 qa = *(const float4*)(Aq + (size_t)r * E + k0 + c4);
            Qs[c4 + 0][r] = qa.x; Qs[c4 + 1][r] = qa.y;
            Qs[c4 + 2][r] = qa.z; Qs[c4 + 3][r] = qa.w;
            float4 ka = *(const float4*)(Ak + (size_t)r * E + k0 + c4);
            Ks[c4 + 0][r] = ka.x; Ks[c4 + 1][r] = ka.y;
            Ks[c4 + 2][r] = ka.z; Ks[c4 + 3][r] = ka.w;
        }
        __syncthreads();
#pragma unroll
        for (int k = 0; k < 32; ++k) {
            float ra[8], rb[8];
            *(float4*)&ra[0] = *(const float4*)&Qs[k][tr];
            *(float4*)&ra[4] = *(const float4*)&Qs[k][tr + 4];
            *(float4*)&rb[0] = *(const float4*)&Ks[k][tc];
            *(float4*)&rb[4] = *(const float4*)&Ks[k][tc + 4];
#pragma unroll
            for (int i = 0; i < 8; ++i)
#pragma unroll
                for (int j = 0; j < 8; ++j)
                    acc[i][j] = fmaf(ra[i], rb[j], acc[i][j]);
        }
        __syncthreads();
    }
    float* Cb = g_draft + ((size_t)h * S + it * 128 + tr) * S + jt * 128 + tc;
#pragma unroll
    for (int i = 0; i < 8; ++i) {
        *(float4*)(Cb + (size_t)i * S)     = make_float4(acc[i][0], acc[i][1], acc[i][2], acc[i][3]);
        *(float4*)(Cb + (size_t)i * S + 4) = make_float4(acc[i][4], acc[i][5], acc[i][6], acc[i][7]);
    }
}

// ---------------- HMMA bf16x3 dense GEMM (V proj + Wo): C = A @ B ----------------
#define A_TILE_B (128 * 80)
#define B_TILE_B (32 * 272)
#define G_STAGE  (2 * A_TILE_B + 2 * B_TILE_B)
#define G_SMEM   (2 * G_STAGE)

__global__ __launch_bounds__(256, 2) void gemm_mma(
    const __nv_bfloat16* __restrict__ Ahi, const __nv_bfloat16* __restrict__ Alo,
    const __nv_bfloat16* __restrict__ Bhi, const __nv_bfloat16* __restrict__ Blo,
    float* __restrict__ C, int M, int N, int K)
{
    extern __shared__ char smem[];
    const int tid = threadIdx.x, lane = tid & 31, wid = tid >> 5;
    const int brow = blockIdx.y * 128, bcol = blockIdx.x * 128;
    const int wm = (wid >> 2) * 64, wn = (wid & 3) * 32;
    const uint32_t sbase = smem_u32(smem);

    const int ar = tid >> 2, ac = tid & 3;
    const int br = tid >> 4, bc = tid & 15;

    auto load_stage = [&](int c, int stg) {
        uint32_t st = sbase + stg * G_STAGE;
#pragma unroll
        for (int rep = 0; rep < 2; ++rep) {
            int r = ar + rep * 64;
            size_t ga = (size_t)(brow + r) * K + c * 32 + ac * 8;
            uint32_t d = st + r * 80 + ac * 16;
            cp16(d, Ahi + ga);
            cp16(d + A_TILE_B, Alo + ga);
        }
#pragma unroll
        for (int rep = 0; rep < 2; ++rep) {
            int r = br + rep * 16;
            size_t gb = (size_t)(c * 32 + r) * N + bcol + bc * 8;
            uint32_t d = st + 2 * A_TILE_B + r * 272 + bc * 16;
            cp16(d, Bhi + gb);
            cp16(d + B_TILE_B, Blo + gb);
        }
    };

    float acc[4][4][4];
#pragma unroll
    for (int i = 0; i < 4; ++i)
#pragma unroll
        for (int j = 0; j < 4; ++j)
#pragma unroll
            for (int f = 0; f < 4; ++f) acc[i][j][f] = 0.f;

    const int NC = K / 32;
    load_stage(0, 0); CP_COMMIT();
    load_stage(1, 1); CP_COMMIT();

    const int arow = (lane & 7) + ((lane >> 3) & 1) * 8;
    const int asel = (lane >> 4) & 1;

    for (int c = 0; c < NC; ++c) {
        CP_WAIT1();
        __syncthreads();
        uint32_t st = sbase + (c & 1) * G_STAGE;
        uint32_t stB = st + 2 * A_TILE_B;
#pragma unroll
        for (int ks = 0; ks < 2; ++ks) {
            const int k0 = ks * 16;
            uint32_t a_f[4][4], b_hi[4][2], b_lo[4][2];
#pragma unroll
            for (int ti = 0; ti < 4; ++ti) {
                uint32_t ad = st + (wm + ti * 16 + arow) * 80 + (k0 + asel * 8) * 2;
                ldm_x4(a_f[ti], ad);
            }
#pragma unroll
            for (int tp = 0; tp < 2; ++tp) {
                int brw = k0 + (lane & 7) + ((lane >> 3) & 1) * 8;
                int bcl = wn + tp * 16 + asel * 8;
                uint32_t bd = stB + brw * 272 + bcl * 2;
                uint32_t r[4];
                ldm_x4_t(r, bd);
                b_hi[tp * 2][0] = r[0]; b_hi[tp * 2][1] = r[1];
                b_hi[tp * 2 + 1][0] = r[2]; b_hi[tp * 2 + 1][1] = r[3];
                ldm_x4_t(r, bd + B_TILE_B);
                b_lo[tp * 2][0] = r[0]; b_lo[tp * 2][1] = r[1];
                b_lo[tp * 2 + 1][0] = r[2]; b_lo[tp * 2 + 1][1] = r[3];
            }
#pragma unroll
            for (int ti = 0; ti < 4; ++ti)
#pragma unroll
                for (int tj = 0; tj < 4; ++tj) {
                    mma16816(acc[ti][tj], a_f[ti], b_hi[tj]);
                    mma16816(acc[ti][tj], a_f[ti], b_lo[tj]);
                }
#pragma unroll
            for (int ti = 0; ti < 4; ++ti) {
                uint32_t ad = st + A_TILE_B + (wm + ti * 16 + arow) * 80 + (k0 + asel * 8) * 2;
                ldm_x4(a_f[ti], ad);
            }
#pragma unroll
            for (int ti = 0; ti < 4; ++ti)
#pragma unroll
                for (int tj = 0; tj < 4; ++tj)
                    mma16816(acc[ti][tj], a_f[ti], b_hi[tj]);
        }
        __syncthreads();
        if (c + 2 < NC) load_stage(c + 2, c & 1);
        CP_COMMIT();
    }

    const int er = lane >> 2, ec = (lane & 3) * 2;
#pragma unroll
    for (int ti = 0; ti < 4; ++ti)
#pragma unroll
        for (int tj = 0; tj < 4; ++tj) {
            int r0 = brow + wm + ti * 16 + er;
            int c0 = bcol + wn + tj * 8 + ec;
            *(float2*)&C[(size_t)r0 * N + c0]       = make_float2(acc[ti][tj][0], acc[ti][tj][1]);
            *(float2*)&C[(size_t)(r0 + 8) * N + c0] = make_float2(acc[ti][tj][2], acc[ti][tj][3]);
        }
}

// ---------------- RoPE apply ----------------
__global__ void rope_apply_kernel()
{
    int s = blockIdx.x;
    for (int e = threadIdx.x; e < E; e += blockDim.x) {
        int d = e & (D - 1);
        float c = g_cos[s * D + d], sn = g_sin[s * D + d];
        size_t o = (size_t)s * E + e;
        int ep = (d < 64) ? e + 64 : e - 64;
        size_t op = (size_t)s * E + ep;
        float sgn = (d < 64) ? -1.f : 1.f;
        g_Qr[o] = g_Q[o] * c + sgn * g_Q[op] * sn;
        g_Kr[o] = g_K[o] * c + sgn * g_K[op] * sn;
    }
}

// ---------------- per-row top-NKEEP (exact radix-select) ----------------
__global__ __launch_bounds__(256) void topk_kernel()
{
    int q = blockIdx.x, h = blockIdx.y, tid = threadIdx.x;
    __shared__ unsigned keys[2048];
    __shared__ int aux[257];
    __shared__ unsigned sh_prefix;
    __shared__ int sh_k, sh_total;
    size_t base = ((size_t)h * S + q) * CAP;
    int n = q + 1;
    if (n <= NKEEP) {
        for (int j = tid; j < n; j += 256) g_idx[base + j] = (unsigned short)j;
        if (tid == 0) g_cnt[h * S + q] = n;
        return;
    }
    const float* row = g_draft + ((size_t)h * S + q) * S;
    for (int j = tid; j < n; j += 256) {
        unsigned u = __float_as_uint(row[j]);
        keys[j] = (u & 0x80000000u) ? ~u : (u | 0x80000000u);
    }
    __syncthreads();
    unsigned prefix = 0, himask = 0;
    int kk = NKEEP;
    for (int byte = 3; byte >= 0; --byte) {
        aux[tid] = 0;
        __syncthreads();
        for (int j = tid; j < n; j += 256) {
            unsigned u = keys[j];
            if ((u & himask) == prefix)
                atomicAdd(&aux[(u >> (byte * 8)) & 255], 1);
        }
        __syncthreads();
        if (tid == 0) {
            int cum = 0, b = 255;
            for (; b > 0; --b) {
                int c = aux[b];
                if (cum + c >= kk) break;
                cum += c;
            }
            sh_prefix = prefix | ((unsigned)b << (byte * 8));
            sh_k = kk - cum;
        }
        __syncthreads();
        prefix = sh_prefix;
        kk = sh_k;
        himask |= 0xFFu << (byte * 8);
        __syncthreads();
    }
    int seg = (n + 255) >> 8;
    int j0 = tid * seg;
    int j1 = min(j0 + seg, n);
    int cnt = 0;
    for (int j = j0; j < j1; ++j) if (keys[j] >= prefix) cnt++;
    aux[tid] = cnt;
    __syncthreads();
    if (tid == 0) {
        int run = 0;
        for (int i = 0; i < 256; ++i) { int c = aux[i]; aux[i] = run; run += c; }
        sh_total = run;
    }
    __syncthreads();
    int p = aux[tid];
    for (int j = j0; j < j1; ++j)
        if (keys[j] >= prefix) { if (p < CAP) g_idx[base + p] = (unsigned short)j; ++p; }
    if (tid == 0) g_cnt[h * S + q] = min(sh_total, CAP);
}

// ---------------- sparse attention ----------------
__global__ __launch_bounds__(128) void attn_kernel()
{
    int q = blockIdx.x, h = blockIdx.y, tid = threadIdx.x;
    __shared__ __align__(16) float qv[D];
    __shared__ float sc[CAP];
    __shared__ unsigned short lj[CAP];
    __shared__ float red[4];
    int n = g_cnt[h * S + q];
    qv[tid] = g_Qr[(size_t)q * E + h * D + tid];
    for (int i = tid; i < n; i += 128) lj[i] = g_idx[((size_t)h * S + q) * CAP + i];
    __syncthreads();
    int lane = tid & 31, w = tid >> 5;
    float4 qf = *(const float4*)&qv[lane * 4];
    for (int i = w; i < n; i += 4) {
        const float* kr = g_Kr + (size_t)lj[i] * E + h * D + lane * 4;
        float4 kf = *(const float4*)kr;
        float s = qf.x * kf.x + qf.y * kf.y + qf.z * kf.z + qf.w * kf.w;
#pragma unroll
        for (int o = 16; o; o >>= 1) s += __shfl_xor_sync(0xffffffffu, s, o);
        if (lane == 0) sc[i] = s * 0.08838834764831845f;
    }
    __syncthreads();
    float mx = -INFINITY;
    for (int i = tid; i < n; i += 128) mx = fmaxf(mx, sc[i]);
#pragma unroll
    for (int o = 16; o; o >>= 1) mx = fmaxf(mx, __shfl_xor_sync(0xffffffffu, mx, o));
    if (lane == 0) red[w] = mx;
    __syncthreads();
    mx = fmaxf(fmaxf(red[0], red[1]), fmaxf(red[2], red[3]));
    __syncthreads();
    float sum = 0.f;
    for (int i = tid; i < n; i += 128) { float e = expf(sc[i] - mx); sc[i] = e; sum += e; }
#pragma unroll
    for (int o = 16; o; o >>= 1) sum += __shfl_xor_sync(0xffffffffu, sum, o);
    if (lane == 0) red[w] = sum;
    __syncthreads();
    sum = red[0] + red[1] + red[2] + red[3];
    float inv = 1.f / sum;
    float acc = 0.f;
    const float* Vb = g_V + h * D + tid;
    for (int i = 0; i < n; ++i)
        acc = fmaf(sc[i], Vb[(size_t)lj[i] * E], acc);
    g_attn[(size_t)q * E + h * D + tid] = acc * inv;
}

// ---------------- host ----------------
extern "C" void kernel_launch(void* const* d_in, const int* in_sizes, int n_in,
                              void* d_out, int out_size)
{
    const float* X  = (const float*)d_in[0];
    const float* Wq = (const float*)d_in[1];
    const float* Wk = (const float*)d_in[2];
    const float* Wv = (const float*)d_in[3];
    const float* Wo = (const float*)d_in[4];
    float* out = (float*)d_out;

    float *pQ, *pK, *pV, *pAt;
    cudaGetSymbolAddress((void**)&pQ, g_Q);
    cudaGetSymbolAddress((void**)&pK, g_K);
    cudaGetSymbolAddress((void**)&pV, g_V);
    cudaGetSymbolAddress((void**)&pAt, g_attn);

    __nv_bfloat16 *xh, *xl, *ah, *al, *wvh, *wvl, *woh, *wol;
    cudaGetSymbolAddress((void**)&xh, g_Xhi);   cudaGetSymbolAddress((void**)&xl, g_Xlo);
    cudaGetSymbolAddress((void**)&ah, g_Ahi);   cudaGetSymbolAddress((void**)&al, g_Alo);
    cudaGetSymbolAddress((void**)&wvh, g_Wvhi); cudaGetSymbolAddress((void**)&wvl, g_Wvlo);
    cudaGetSymbolAddress((void**)&woh, g_Wohi); cudaGetSymbolAddress((void**)&wol, g_Wolo);

    cudaFuncSetAttribute(gemm_mma, cudaFuncAttributeMaxDynamicSharedMemorySize, G_SMEM);

    const int nSE4 = S * E / 4, nEE4 = E * E / 4;
    dim3 gg(E / 128, S / 128);

    rope_cache_kernel<<<S, 64>>>();
    cvt_kernel<<<(nSE4 + 255) / 256, 256>>>(X, xh, xl, nSE4);
    cvt_kernel<<<(nEE4 + 255) / 256, 256>>>(Wv, wvh, wvl, nEE4);
    cvt_kernel<<<(nEE4 + 255) / 256, 256>>>(Wo, woh, wol, nEE4);

    // Selection-critical path: exact fp32 (R4-proven)
    sgemm_nn<<<gg, 256>>>(X, Wq, pQ, S, E, E);
    sgemm_nn<<<gg, 256>>>(X, Wk, pK, S, E, E);
    // Non-selection-critical: HMMA bf16x3
    gemm_mma<<<gg, 256, G_SMEM>>>(xh, xl, wvh, wvl, pV, S, E, E);

    rope_apply_kernel<<<S, 256>>>();
    draft_gemm_kernel<<<dim3(16, 16, 32), 256>>>();
    topk_kernel<<<dim3(S, H), 256>>>();
    attn_kernel<<<dim3(S, H), 128>>>();

    cvt_kernel<<<(nSE4 + 255) / 256, 256>>>(pAt, ah, al, nSE4);
    gemm_mma<<<gg, 256, G_SMEM>>>(ah, al, woh, wol, out, S, E, E);
}